// round 14
// baseline (speedup 1.0000x reference)
#include <cuda_runtime.h>
#include <cstdint>

// ---------------------------------------------------------------------------
// Problem constants
// ---------------------------------------------------------------------------
#define OUT_DIM 4096
#define IN_DIM  4096
#define M_TOTAL 8192                 // 4 * 2048
#define R_DIM   64

// Scratch (allocation-free rule), plain row-major layout.
__device__ float g_W[(size_t)OUT_DIM * IN_DIM];  // rna(deq W + 2 B@A)
__device__ float g_X[(size_t)M_TOTAL * IN_DIM];  // rna(x)

__constant__ float c_nf4[16] = {
    -1.0f, -0.6961928009986877f, -0.5250730514526367f, -0.39491748809814453f,
    -0.28444138169288635f, -0.18477343022823334f, -0.09105003625154495f, 0.0f,
    0.07958029955625534f, 0.16093020141124725f, 0.24611230194568634f, 0.33791524171829224f,
    0.44070982933044434f, 0.5626170039176941f, 0.7229568362236023f, 1.0f};

// ---------------------------------------------------------------------------
// Helpers
// ---------------------------------------------------------------------------
__device__ __forceinline__ float rna_tf32(float v) {
    uint32_t r;
    asm("cvt.rna.tf32.f32 %0, %1;" : "=r"(r) : "f"(v));
    return __uint_as_float(r);
}

__device__ __forceinline__ void cp_async16(void* smem_dst, const void* gptr) {
    uint32_t s = (uint32_t)__cvta_generic_to_shared(smem_dst);
    asm volatile("cp.async.cg.shared.global [%0], [%1], 16;" :: "r"(s), "l"(gptr));
}
__device__ __forceinline__ void cp_commit() {
    asm volatile("cp.async.commit_group;" ::: "memory");
}
template <int N>
__device__ __forceinline__ void cp_wait() {
    asm volatile("cp.async.wait_group %0;" :: "n"(N) : "memory");
}

// tf32: D += A(16x8) * B(8x8)
__device__ __forceinline__ void mma_tf32(float* c, const uint32_t* a, const uint32_t* b) {
    asm volatile(
        "mma.sync.aligned.m16n8k8.row.col.f32.tf32.tf32.f32 "
        "{%0,%1,%2,%3}, {%4,%5,%6,%7}, {%8,%9}, {%0,%1,%2,%3};"
        : "+f"(c[0]), "+f"(c[1]), "+f"(c[2]), "+f"(c[3])
        : "r"(a[0]), "r"(a[1]), "r"(a[2]), "r"(a[3]), "r"(b[0]), "r"(b[1]));
}

// ldmatrix x4: four 8x8xb16 tiles (== 8x4xb32), lane l gets b32 (row l/4, col l%4)
#define LDSM_X4(r0, r1, r2, r3, addr) \
    asm volatile("ldmatrix.sync.aligned.m8n8.x4.shared.b16 {%0,%1,%2,%3}, [%4];" \
                 : "=r"(r0), "=r"(r1), "=r"(r2), "=r"(r3) : "r"(addr))

extern __shared__ char smem_raw[];

// ---------------------------------------------------------------------------
// Launch 1: prep_w — W' 128x128 tiles = rna(deq_nf4 + 2*B@A)
// ---------------------------------------------------------------------------
__global__ __launch_bounds__(256)
void prep_w(const float* __restrict__ lora_A,   // [64][4096]
            const float* __restrict__ lora_B,   // [4096][64]
            const float* __restrict__ absmax,   // [262144]
            const int*   __restrict__ codes) {  // [4096][4096]
    constexpr int PAD = 132;
    float* sBt = reinterpret_cast<float*>(smem_raw);  // [64][132] B^T
    float* sA  = sBt + 64 * PAD;                      // [64][132] A
    const int b = blockIdx.x, tid = threadIdx.x;
    const int n0 = (b >> 5) * 128, k0 = (b & 31) * 128;

    for (int idx = tid; idx < 128 * 16; idx += 256) {
        int row = idx & 127, rq = idx >> 7;
        float4 v = *reinterpret_cast<const float4*>(&lora_B[(size_t)(n0 + row) * R_DIM + rq * 4]);
        sBt[(rq * 4 + 0) * PAD + row] = v.x;
        sBt[(rq * 4 + 1) * PAD + row] = v.y;
        sBt[(rq * 4 + 2) * PAD + row] = v.z;
        sBt[(rq * 4 + 3) * PAD + row] = v.w;
    }
    for (int idx = tid; idx < 64 * 32; idx += 256) {
        int r = idx >> 5, c4 = idx & 31;
        *reinterpret_cast<float4*>(&sA[r * PAD + c4 * 4]) =
            *reinterpret_cast<const float4*>(&lora_A[(size_t)r * IN_DIM + k0 + c4 * 4]);
    }
    __syncthreads();

    const int ty = tid >> 4, tx = tid & 15;           // 16x16 thread grid
    float acc[8][8];
#pragma unroll
    for (int i = 0; i < 8; i++)
#pragma unroll
        for (int j = 0; j < 8; j++) acc[i][j] = 0.0f;

    for (int r = 0; r < R_DIM; r++) {
        float bv[8], av[8];
        float4 b0 = *reinterpret_cast<const float4*>(&sBt[r * PAD + ty * 8]);
        float4 b1 = *reinterpret_cast<const float4*>(&sBt[r * PAD + ty * 8 + 4]);
        float4 a0 = *reinterpret_cast<const float4*>(&sA[r * PAD + tx * 8]);
        float4 a1 = *reinterpret_cast<const float4*>(&sA[r * PAD + tx * 8 + 4]);
        bv[0] = b0.x; bv[1] = b0.y; bv[2] = b0.z; bv[3] = b0.w;
        bv[4] = b1.x; bv[5] = b1.y; bv[6] = b1.z; bv[7] = b1.w;
        av[0] = a0.x; av[1] = a0.y; av[2] = a0.z; av[3] = a0.w;
        av[4] = a1.x; av[5] = a1.y; av[6] = a1.z; av[7] = a1.w;
#pragma unroll
        for (int i = 0; i < 8; i++)
#pragma unroll
            for (int j = 0; j < 8; j++) acc[i][j] = fmaf(bv[i], av[j], acc[i][j]);
    }

#pragma unroll
    for (int i = 0; i < 8; i++) {
        int n = n0 + ty * 8 + i;
        int k = k0 + tx * 8;
        float am = absmax[n * 64 + (k >> 6)];
        const int4* cp = reinterpret_cast<const int4*>(&codes[(size_t)n * IN_DIM + k]);
        int4 c0 = cp[0], c1 = cp[1];
        float4 o0, o1;
        o0.x = rna_tf32(fmaf(c_nf4[c0.x & 15], am, 2.0f * acc[i][0]));
        o0.y = rna_tf32(fmaf(c_nf4[c0.y & 15], am, 2.0f * acc[i][1]));
        o0.z = rna_tf32(fmaf(c_nf4[c0.z & 15], am, 2.0f * acc[i][2]));
        o0.w = rna_tf32(fmaf(c_nf4[c0.w & 15], am, 2.0f * acc[i][3]));
        o1.x = rna_tf32(fmaf(c_nf4[c1.x & 15], am, 2.0f * acc[i][4]));
        o1.y = rna_tf32(fmaf(c_nf4[c1.y & 15], am, 2.0f * acc[i][5]));
        o1.z = rna_tf32(fmaf(c_nf4[c1.z & 15], am, 2.0f * acc[i][6]));
        o1.w = rna_tf32(fmaf(c_nf4[c1.w & 15], am, 2.0f * acc[i][7]));
        float4* op = reinterpret_cast<float4*>(&g_W[(size_t)n * IN_DIM + k]);
        op[0] = o0;
        op[1] = o1;
    }
}

// ---------------------------------------------------------------------------
// Launch 2: prep_x — g_X = rna(x), dedicated streaming kernel
// ---------------------------------------------------------------------------
__global__ __launch_bounds__(256)
void prep_x(const float4* __restrict__ x4) {
    const int n4 = M_TOTAL * IN_DIM / 4;          // 8388608
    float4* o = reinterpret_cast<float4*>(g_X);
    for (int i = blockIdx.x * 256 + threadIdx.x; i < n4; i += gridDim.x * 256) {
        float4 v = x4[i];
        v.x = rna_tf32(v.x); v.y = rna_tf32(v.y);
        v.z = rna_tf32(v.z); v.w = rna_tf32(v.w);
        o[i] = v;
    }
}

// ---------------------------------------------------------------------------
// Launch 3: main tf32 GEMM  out = x @ W'^T   (K = 4096)
//   CTA 256x128, 256 thr, warps 4(m)x2(n) of 64x64, BK=32, 3 stages,
//   1 CTA/SM (166 KB smem), GROUP=4 swizzle, SA=36 pad.
//   Warp tile 64x64 halves smem-crossbar read amplification vs 64x32
//   (A amp x2, B amp x4 on half-size B) -> crossbar no longer co-binding.
//   ldmatrix.x4 fragments + ks double-buffering + kt unroll by 3.
// ---------------------------------------------------------------------------
__global__ __launch_bounds__(256, 1)
void gemm_main(float* __restrict__ out) {
    constexpr int BM = 256, BN = 128, SA = 36, STAGES = 3;
    constexpr int MT = 4, NT = 8;                 // warp tile 64x64
    constexpr int GROUP = 4, NBLK = OUT_DIM / BN; // 32
    constexpr int SAB = SA * 4;                   // 144 B row stride
    constexpr int A_STAGE_B = BM * SAB;           // 36864 B
    constexpr int B_STAGE_B = BN * SAB;           // 18432 B
    constexpr int NK = IN_DIM / 32;               // 128 kt iterations

    float* smem = reinterpret_cast<float*>(smem_raw);
    float* sA = smem;                             // [3][256*36]
    float* sB = smem + STAGES * BM * SA;          // [3][128*36]

    const int tid = threadIdx.x, lane = tid & 31, wid = tid >> 5;
    const int wm = wid & 3, wn = wid >> 2;        // 4(m) x 2(n) warps
    const int lr = lane >> 2, lc = lane & 3;

    const int bid = blockIdx.x;
    const int grp = bid / (GROUP * NBLK);
    const int rem = bid % (GROUP * NBLK);
    const int m0 = (grp * GROUP + rem % GROUP) * BM;
    const int n0 = (rem / GROUP) * BN;

    const float* gA = g_X + (size_t)m0 * IN_DIM;
    const float* gB = g_W + (size_t)n0 * IN_DIM;

    const uint32_t sA_u = (uint32_t)__cvta_generic_to_shared(sA);
    const uint32_t sB_u = (uint32_t)__cvta_generic_to_shared(sB);
    // A ldmatrix.x4 (per mt): mats (r0-7,c0-3),(r8-15,c0-3),(r0-7,c4-7),(r8-15,c4-7)
    const uint32_t aAddr0 = sA_u + (uint32_t)(((wm * 64 + (lane & 15)) * SA + (lane >> 4) * 4) * 4);
    // B ldmatrix.x4 (per nt-pair p): mats (nt0,c0-3),(nt0,c4-7),(nt1,c0-3),(nt1,c4-7)
    const uint32_t bAddr0 = sB_u + (uint32_t)(((wn * 64 + ((lane >> 4) << 3) + (lane & 7)) * SA
                                               + ((lane >> 3) & 1) * 4) * 4);

    float c[MT][NT][4];
#pragma unroll
    for (int mt = 0; mt < MT; mt++)
#pragma unroll
        for (int nt = 0; nt < NT; nt++)
#pragma unroll
            for (int q = 0; q < 4; q++) c[mt][nt][q] = 0.0f;

    // Per-thread cp.async coordinates (fixed)
    const int ld_row = tid >> 3, ld_col = (tid & 7) * 4;

    auto load_stage = [&](int s, int kt) {
        const int kk = kt * 32;
        float* dA = sA + s * BM * SA;
        float* dB = sB + s * BN * SA;
#pragma unroll
        for (int i = 0; i < 8; i++) {             // A: 2048 chunks / 256 thr
            int row = ld_row + 32 * i;
            cp_async16(dA + row * SA + ld_col, gA + (size_t)row * IN_DIM + kk + ld_col);
        }
#pragma unroll
        for (int i = 0; i < 4; i++) {             // B: 1024 chunks
            int row = ld_row + 32 * i;
            cp_async16(dB + row * SA + ld_col, gB + (size_t)row * IN_DIM + kk + ld_col);
        }
    };

    uint32_t af[2][MT][4], bf[2][NT][2];

    auto load_frags = [&](int s, int ks, int buf) {
        uint32_t aS = aAddr0 + s * A_STAGE_B + ks * 32;
        uint32_t bS = bAddr0 + s * B_STAGE_B + ks * 32;
#pragma unroll
        for (int mt = 0; mt < MT; mt++)
            LDSM_X4(af[buf][mt][0], af[buf][mt][1], af[buf][mt][2], af[buf][mt][3],
                    aS + mt * 16 * SAB);
#pragma unroll
        for (int p = 0; p < 4; p++)
            LDSM_X4(bf[buf][2 * p][0], bf[buf][2 * p][1],
                    bf[buf][2 * p + 1][0], bf[buf][2 * p + 1][1],
                    bS + p * 16 * SAB);
    };

    // One kt iteration with compile-time stage indices.
    auto kt_iter = [&](int kt, int s, int ls_stage, bool do_load) {
        load_frags(s, 0, 0);                      // ks0 LDSM first
        if (do_load) load_stage(ls_stage, kt + 2);
        cp_commit();
#pragma unroll
        for (int ks = 0; ks < 4; ks++) {
            int cur = ks & 1;
            if (ks < 3) load_frags(s, ks + 1, cur ^ 1);
#pragma unroll
            for (int mt = 0; mt < MT; mt++)
#pragma unroll
                for (int nt = 0; nt < NT; nt++)
                    mma_tf32(c[mt][nt], af[cur][mt], bf[cur][nt]);
        }
        cp_wait<1>();
        __syncthreads();
    };

    load_stage(0, 0); cp_commit();
    load_stage(1, 1); cp_commit();
    cp_wait<1>();
    __syncthreads();

    for (int kt = 0; kt < NK - 2; kt += 3) {
        kt_iter(kt,     0, 2, true);
        kt_iter(kt + 1, 1, 0, true);
        kt_iter(kt + 2, 2, 1, true);
    }
    kt_iter(NK - 2, 0, 2, false);
    kt_iter(NK - 1, 1, 0, false);

    // Epilogue
#pragma unroll
    for (int mt = 0; mt < MT; mt++) {
        int r0 = m0 + wm * 64 + mt * 16 + lr;
#pragma unroll
        for (int nt = 0; nt < NT; nt++) {
            int cc = n0 + wn * 64 + nt * 8 + 2 * lc;
            *reinterpret_cast<float2*>(&out[(size_t)r0 * OUT_DIM + cc]) =
                make_float2(c[mt][nt][0], c[mt][nt][1]);
            *reinterpret_cast<float2*>(&out[(size_t)(r0 + 8) * OUT_DIM + cc]) =
                make_float2(c[mt][nt][2], c[mt][nt][3]);
        }
    }
}

// ---------------------------------------------------------------------------
// Host
// ---------------------------------------------------------------------------
extern "C" void kernel_launch(void* const* d_in, const int* in_sizes, int n_in,
                              void* d_out, int out_size) {
    const float* x      = (const float*)d_in[0];
    const float* lora_A = (const float*)d_in[1];
    const float* lora_B = (const float*)d_in[2];
    const float* absmax = (const float*)d_in[3];
    const int*   codes  = (const int*)d_in[4];
    float* out = (float*)d_out;

    constexpr int SMEM_PREP = 2 * 64 * 132 * 4;          //  67584
    constexpr int SMEM_MAIN = 3 * (256 + 128) * 36 * 4;  // 165888 -> 1 CTA/SM
    static bool attr_done = false;
    if (!attr_done) {
        cudaFuncSetAttribute((const void*)prep_w,
                             cudaFuncAttributeMaxDynamicSharedMemorySize, SMEM_PREP);
        cudaFuncSetAttribute((const void*)gemm_main,
                             cudaFuncAttributeMaxDynamicSharedMemorySize, SMEM_MAIN);
        attr_done = true;
    }

    // 1) W' = rna(deq + 2 B@A)
    prep_w<<<1024, 256, SMEM_PREP>>>(lora_A, lora_B, absmax, codes);

    // 2) g_X = rna(x)  (dedicated streaming kernel, full-chip)
    prep_x<<<8192, 256>>>((const float4*)x);

    // 3) out = x @ W'^T
    gemm_main<<<(M_TOTAL / 256) * (OUT_DIM / 128), 256, SMEM_MAIN>>>(out);
}

// round 15
// speedup vs baseline: 1.1051x; 1.1051x over previous
#include <cuda_runtime.h>
#include <cstdint>

// ---------------------------------------------------------------------------
// Problem constants
// ---------------------------------------------------------------------------
#define OUT_DIM 4096
#define IN_DIM  4096
#define M_TOTAL 8192                 // 4 * 2048
#define R_DIM   64

// Scratch (allocation-free rule), plain row-major layout.
// W' = rna_tf32( dequant_nf4(W) + 2 * lora_B @ lora_A )
__device__ float g_W[(size_t)OUT_DIM * IN_DIM];

__constant__ float c_nf4[16] = {
    -1.0f, -0.6961928009986877f, -0.5250730514526367f, -0.39491748809814453f,
    -0.28444138169288635f, -0.18477343022823334f, -0.09105003625154495f, 0.0f,
    0.07958029955625534f, 0.16093020141124725f, 0.24611230194568634f, 0.33791524171829224f,
    0.44070982933044434f, 0.5626170039176941f, 0.7229568362236023f, 1.0f};

// ---------------------------------------------------------------------------
// Helpers
// ---------------------------------------------------------------------------
__device__ __forceinline__ float rna_tf32(float v) {
    uint32_t r;
    asm("cvt.rna.tf32.f32 %0, %1;" : "=r"(r) : "f"(v));
    return __uint_as_float(r);
}

__device__ __forceinline__ void cp_async16(void* smem_dst, const void* gptr) {
    uint32_t s = (uint32_t)__cvta_generic_to_shared(smem_dst);
    asm volatile("cp.async.cg.shared.global [%0], [%1], 16;" :: "r"(s), "l"(gptr));
}
__device__ __forceinline__ void cp_commit() {
    asm volatile("cp.async.commit_group;" ::: "memory");
}
template <int N>
__device__ __forceinline__ void cp_wait() {
    asm volatile("cp.async.wait_group %0;" :: "n"(N) : "memory");
}

// tf32: D += A(16x8) * B(8x8)
// NOTE: raw fp32 bits in operands are consumed as tf32 via HW truncation.
__device__ __forceinline__ void mma_tf32(float* c, const uint32_t* a, const uint32_t* b) {
    asm volatile(
        "mma.sync.aligned.m16n8k8.row.col.f32.tf32.tf32.f32 "
        "{%0,%1,%2,%3}, {%4,%5,%6,%7}, {%8,%9}, {%0,%1,%2,%3};"
        : "+f"(c[0]), "+f"(c[1]), "+f"(c[2]), "+f"(c[3])
        : "r"(a[0]), "r"(a[1]), "r"(a[2]), "r"(a[3]), "r"(b[0]), "r"(b[1]));
}

// ldmatrix x4: four 8x8xb16 tiles (== 8x4xb32), lane l gets b32 (row l/4, col l%4)
#define LDSM_X4(r0, r1, r2, r3, addr) \
    asm volatile("ldmatrix.sync.aligned.m8n8.x4.shared.b16 {%0,%1,%2,%3}, [%4];" \
                 : "=r"(r0), "=r"(r1), "=r"(r2), "=r"(r3) : "r"(addr))

extern __shared__ char smem_raw[];

// ---------------------------------------------------------------------------
// Launch 1: prep_w — W' 128x128 tiles = rna(deq_nf4 + 2*B@A)
//   (x is NOT pre-rounded anymore: the GEMM feeds raw fp32 x to mma.sync,
//    which truncates to tf32 in HW. W' stays rna-rounded, so the W-side
//    error keeps round-to-nearest statistics.)
// ---------------------------------------------------------------------------
__global__ __launch_bounds__(256)
void prep_w(const float* __restrict__ lora_A,   // [64][4096]
            const float* __restrict__ lora_B,   // [4096][64]
            const float* __restrict__ absmax,   // [262144]
            const int*   __restrict__ codes) {  // [4096][4096]
    constexpr int PAD = 132;
    float* sBt = reinterpret_cast<float*>(smem_raw);  // [64][132] B^T
    float* sA  = sBt + 64 * PAD;                      // [64][132] A
    const int b = blockIdx.x, tid = threadIdx.x;
    const int n0 = (b >> 5) * 128, k0 = (b & 31) * 128;

    for (int idx = tid; idx < 128 * 16; idx += 256) {
        int row = idx & 127, rq = idx >> 7;
        float4 v = *reinterpret_cast<const float4*>(&lora_B[(size_t)(n0 + row) * R_DIM + rq * 4]);
        sBt[(rq * 4 + 0) * PAD + row] = v.x;
        sBt[(rq * 4 + 1) * PAD + row] = v.y;
        sBt[(rq * 4 + 2) * PAD + row] = v.z;
        sBt[(rq * 4 + 3) * PAD + row] = v.w;
    }
    for (int idx = tid; idx < 64 * 32; idx += 256) {
        int r = idx >> 5, c4 = idx & 31;
        *reinterpret_cast<float4*>(&sA[r * PAD + c4 * 4]) =
            *reinterpret_cast<const float4*>(&lora_A[(size_t)r * IN_DIM + k0 + c4 * 4]);
    }
    __syncthreads();

    const int ty = tid >> 4, tx = tid & 15;           // 16x16 thread grid
    float acc[8][8];
#pragma unroll
    for (int i = 0; i < 8; i++)
#pragma unroll
        for (int j = 0; j < 8; j++) acc[i][j] = 0.0f;

    for (int r = 0; r < R_DIM; r++) {
        float bv[8], av[8];
        float4 b0 = *reinterpret_cast<const float4*>(&sBt[r * PAD + ty * 8]);
        float4 b1 = *reinterpret_cast<const float4*>(&sBt[r * PAD + ty * 8 + 4]);
        float4 a0 = *reinterpret_cast<const float4*>(&sA[r * PAD + tx * 8]);
        float4 a1 = *reinterpret_cast<const float4*>(&sA[r * PAD + tx * 8 + 4]);
        bv[0] = b0.x; bv[1] = b0.y; bv[2] = b0.z; bv[3] = b0.w;
        bv[4] = b1.x; bv[5] = b1.y; bv[6] = b1.z; bv[7] = b1.w;
        av[0] = a0.x; av[1] = a0.y; av[2] = a0.z; av[3] = a0.w;
        av[4] = a1.x; av[5] = a1.y; av[6] = a1.z; av[7] = a1.w;
#pragma unroll
        for (int i = 0; i < 8; i++)
#pragma unroll
            for (int j = 0; j < 8; j++) acc[i][j] = fmaf(bv[i], av[j], acc[i][j]);
    }

#pragma unroll
    for (int i = 0; i < 8; i++) {
        int n = n0 + ty * 8 + i;
        int k = k0 + tx * 8;
        float am = absmax[n * 64 + (k >> 6)];
        const int4* cp = reinterpret_cast<const int4*>(&codes[(size_t)n * IN_DIM + k]);
        int4 c0 = cp[0], c1 = cp[1];
        float4 o0, o1;
        o0.x = rna_tf32(fmaf(c_nf4[c0.x & 15], am, 2.0f * acc[i][0]));
        o0.y = rna_tf32(fmaf(c_nf4[c0.y & 15], am, 2.0f * acc[i][1]));
        o0.z = rna_tf32(fmaf(c_nf4[c0.z & 15], am, 2.0f * acc[i][2]));
        o0.w = rna_tf32(fmaf(c_nf4[c0.w & 15], am, 2.0f * acc[i][3]));
        o1.x = rna_tf32(fmaf(c_nf4[c1.x & 15], am, 2.0f * acc[i][4]));
        o1.y = rna_tf32(fmaf(c_nf4[c1.y & 15], am, 2.0f * acc[i][5]));
        o1.z = rna_tf32(fmaf(c_nf4[c1.z & 15], am, 2.0f * acc[i][6]));
        o1.w = rna_tf32(fmaf(c_nf4[c1.w & 15], am, 2.0f * acc[i][7]));
        float4* op = reinterpret_cast<float4*>(&g_W[(size_t)n * IN_DIM + k]);
        op[0] = o0;
        op[1] = o1;
    }
}

// ---------------------------------------------------------------------------
// Launch 2: main tf32 GEMM  out = x @ W'^T   (K = 4096)
//   R13 proven config: CTA 128x128, 256 thr, warps 2(m)x4(n) of 64x32,
//   BK=32, 3 stages, 2 CTAs/SM, GROUP=8 swizzle, SA=36 pad,
//   ldmatrix.x4 fragments + ks double-buffering + kt unroll by 3.
//   A reads raw x from the input (HW tf32 truncation in the MMA).
// ---------------------------------------------------------------------------
__global__ __launch_bounds__(256, 2)
void gemm_main(const float* __restrict__ x, float* __restrict__ out) {
    constexpr int BM = 128, BN = 128, SA = 36, STAGES = 3;
    constexpr int MT = 4, NT = 4;                 // warp tile 64x32
    constexpr int GROUP = 8, NBLK = OUT_DIM / BN; // 32
    constexpr int SAB = SA * 4;                   // 144 B row stride
    constexpr int A_STAGE_B = BM * SAB;           // 18432 B
    constexpr int B_STAGE_B = BN * SAB;
    constexpr int NK = IN_DIM / 32;               // 128 kt iterations

    float* smem = reinterpret_cast<float*>(smem_raw);
    float* sA = smem;                             // [3][128*36]
    float* sB = smem + STAGES * BM * SA;          // [3][128*36]

    const int tid = threadIdx.x, lane = tid & 31, wid = tid >> 5;
    const int wm = wid & 1, wn = wid >> 1;        // 2 x 4 warps
    const int lr = lane >> 2, lc = lane & 3;

    const int bid = blockIdx.x;
    const int grp = bid / (GROUP * NBLK);
    const int rem = bid % (GROUP * NBLK);
    const int m0 = (grp * GROUP + rem % GROUP) * BM;
    const int n0 = (rem / GROUP) * BN;

    const float* gA = x + (size_t)m0 * IN_DIM;
    const float* gB = g_W + (size_t)n0 * IN_DIM;

    const uint32_t sA_u = (uint32_t)__cvta_generic_to_shared(sA);
    const uint32_t sB_u = (uint32_t)__cvta_generic_to_shared(sB);
    const uint32_t aAddr0 = sA_u + (uint32_t)(((wm * 64 + (lane & 15)) * SA + (lane >> 4) * 4) * 4);
    const uint32_t bAddr0 = sB_u + (uint32_t)(((wn * 32 + ((lane >> 4) << 3) + (lane & 7)) * SA
                                               + ((lane >> 3) & 1) * 4) * 4);

    float c[MT][NT][4];
#pragma unroll
    for (int mt = 0; mt < MT; mt++)
#pragma unroll
        for (int nt = 0; nt < NT; nt++)
#pragma unroll
            for (int q = 0; q < 4; q++) c[mt][nt][q] = 0.0f;

    // Per-thread cp.async coordinates (fixed)
    const int ld_row = tid >> 3, ld_col = (tid & 7) * 4;

    auto load_stage = [&](int s, int kt) {
        const int kk = kt * 32;
        float* dA = sA + s * BM * SA;
        float* dB = sB + s * BN * SA;
#pragma unroll
        for (int i = 0; i < 4; i++) {             // A: 1024 chunks / 256 thr
            int row = ld_row + 32 * i;
            cp_async16(dA + row * SA + ld_col, gA + (size_t)row * IN_DIM + kk + ld_col);
        }
#pragma unroll
        for (int i = 0; i < 4; i++) {             // B: 1024 chunks
            int row = ld_row + 32 * i;
            cp_async16(dB + row * SA + ld_col, gB + (size_t)row * IN_DIM + kk + ld_col);
        }
    };

    uint32_t af[2][MT][4], bf[2][NT][2];

    auto load_frags = [&](int s, int ks, int buf) {
        uint32_t aS = aAddr0 + s * A_STAGE_B + ks * 32;
        uint32_t bS = bAddr0 + s * B_STAGE_B + ks * 32;
#pragma unroll
        for (int mt = 0; mt < MT; mt++)
            LDSM_X4(af[buf][mt][0], af[buf][mt][1], af[buf][mt][2], af[buf][mt][3],
                    aS + mt * 16 * SAB);
#pragma unroll
        for (int p = 0; p < 2; p++)
            LDSM_X4(bf[buf][2 * p][0], bf[buf][2 * p][1],
                    bf[buf][2 * p + 1][0], bf[buf][2 * p + 1][1],
                    bS + p * 16 * SAB);
    };

    // One kt iteration with compile-time stage indices.
    auto kt_iter = [&](int kt, int s, int ls_stage, bool do_load) {
        load_frags(s, 0, 0);                      // ks0 LDSM first (overlaps cp.async)
        if (do_load) load_stage(ls_stage, kt + 2);
        cp_commit();
#pragma unroll
        for (int ks = 0; ks < 4; ks++) {
            int cur = ks & 1;
            if (ks < 3) load_frags(s, ks + 1, cur ^ 1);
#pragma unroll
            for (int mt = 0; mt < MT; mt++)
#pragma unroll
                for (int nt = 0; nt < NT; nt++)
                    mma_tf32(c[mt][nt], af[cur][mt], bf[cur][nt]);
        }
        cp_wait<1>();
        __syncthreads();
    };

    load_stage(0, 0); cp_commit();
    load_stage(1, 1); cp_commit();
    cp_wait<1>();
    __syncthreads();

    // Steady state: kt in [0,126), unrolled by 3 with constant stage indices
    for (int kt = 0; kt < NK - 2; kt += 3) {
        kt_iter(kt,     0, 2, true);
        kt_iter(kt + 1, 1, 0, true);
        kt_iter(kt + 2, 2, 1, true);
    }
    // Tail: kt = 126 (s=0), kt = 127 (s=1); no further loads
    kt_iter(NK - 2, 0, 2, false);
    kt_iter(NK - 1, 1, 0, false);

    // Epilogue
#pragma unroll
    for (int mt = 0; mt < MT; mt++) {
        int r0 = m0 + wm * 64 + mt * 16 + lr;
#pragma unroll
        for (int nt = 0; nt < NT; nt++) {
            int cc = n0 + wn * 32 + nt * 8 + 2 * lc;
            *reinterpret_cast<float2*>(&out[(size_t)r0 * OUT_DIM + cc]) =
                make_float2(c[mt][nt][0], c[mt][nt][1]);
            *reinterpret_cast<float2*>(&out[(size_t)(r0 + 8) * OUT_DIM + cc]) =
                make_float2(c[mt][nt][2], c[mt][nt][3]);
        }
    }
}

// ---------------------------------------------------------------------------
// Host
// ---------------------------------------------------------------------------
extern "C" void kernel_launch(void* const* d_in, const int* in_sizes, int n_in,
                              void* d_out, int out_size) {
    const float* x      = (const float*)d_in[0];
    const float* lora_A = (const float*)d_in[1];
    const float* lora_B = (const float*)d_in[2];
    const float* absmax = (const float*)d_in[3];
    const int*   codes  = (const int*)d_in[4];
    float* out = (float*)d_out;

    constexpr int SMEM_PREP = 2 * 64 * 132 * 4;          //  67584
    constexpr int SMEM_MAIN = 3 * (128 + 128) * 36 * 4;  // 110592 -> 2 CTA/SM
    static bool attr_done = false;
    if (!attr_done) {
        cudaFuncSetAttribute((const void*)prep_w,
                             cudaFuncAttributeMaxDynamicSharedMemorySize, SMEM_PREP);
        cudaFuncSetAttribute((const void*)gemm_main,
                             cudaFuncAttributeMaxDynamicSharedMemorySize, SMEM_MAIN);
        attr_done = true;
    }

    // 1) W' = rna(deq + 2 B@A)
    prep_w<<<1024, 256, SMEM_PREP>>>(lora_A, lora_B, absmax, codes);

    // 2) out = x @ W'^T  (x fed raw; tf32 truncation happens in the MMA)
    gemm_main<<<(M_TOTAL / 128) * (OUT_DIM / 128), 256, SMEM_MAIN>>>(x, out);
}

// round 16
// speedup vs baseline: 1.1241x; 1.0172x over previous
#include <cuda_runtime.h>
#include <cstdint>

// ---------------------------------------------------------------------------
// Problem constants
// ---------------------------------------------------------------------------
#define OUT_DIM 4096
#define IN_DIM  4096
#define M_TOTAL 8192                 // 4 * 2048
#define R_DIM   64

// Scratch (allocation-free rule), plain row-major layout.
// W' = rna_tf32( dequant_nf4(W) + 2 * lora_B @ lora_A )
__device__ float g_W[(size_t)OUT_DIM * IN_DIM];

__constant__ float c_nf4[16] = {
    -1.0f, -0.6961928009986877f, -0.5250730514526367f, -0.39491748809814453f,
    -0.28444138169288635f, -0.18477343022823334f, -0.09105003625154495f, 0.0f,
    0.07958029955625534f, 0.16093020141124725f, 0.24611230194568634f, 0.33791524171829224f,
    0.44070982933044434f, 0.5626170039176941f, 0.7229568362236023f, 1.0f};

// ---------------------------------------------------------------------------
// Helpers
// ---------------------------------------------------------------------------
__device__ __forceinline__ float rna_tf32(float v) {
    uint32_t r;
    asm("cvt.rna.tf32.f32 %0, %1;" : "=r"(r) : "f"(v));
    return __uint_as_float(r);
}

__device__ __forceinline__ void cp_async16(void* smem_dst, const void* gptr) {
    uint32_t s = (uint32_t)__cvta_generic_to_shared(smem_dst);
    asm volatile("cp.async.cg.shared.global [%0], [%1], 16;" :: "r"(s), "l"(gptr));
}
__device__ __forceinline__ void cp_commit() {
    asm volatile("cp.async.commit_group;" ::: "memory");
}
template <int N>
__device__ __forceinline__ void cp_wait() {
    asm volatile("cp.async.wait_group %0;" :: "n"(N) : "memory");
}

// tf32: D += A(16x8) * B(8x8)
// NOTE: raw fp32 bits in operands are consumed as tf32 via HW truncation.
__device__ __forceinline__ void mma_tf32(float* c, const uint32_t* a, const uint32_t* b) {
    asm volatile(
        "mma.sync.aligned.m16n8k8.row.col.f32.tf32.tf32.f32 "
        "{%0,%1,%2,%3}, {%4,%5,%6,%7}, {%8,%9}, {%0,%1,%2,%3};"
        : "+f"(c[0]), "+f"(c[1]), "+f"(c[2]), "+f"(c[3])
        : "r"(a[0]), "r"(a[1]), "r"(a[2]), "r"(a[3]), "r"(b[0]), "r"(b[1]));
}

// ldmatrix x4: four 8x8xb16 tiles (== 8x4xb32), lane l gets b32 (row l/4, col l%4)
#define LDSM_X4(r0, r1, r2, r3, addr) \
    asm volatile("ldmatrix.sync.aligned.m8n8.x4.shared.b16 {%0,%1,%2,%3}, [%4];" \
                 : "=r"(r0), "=r"(r1), "=r"(r2), "=r"(r3) : "r"(addr))

extern __shared__ char smem_raw[];

// ---------------------------------------------------------------------------
// Launch 1: prep_w — W' 128x128 tiles = rna(deq_nf4 + 2*B@A)  (unchanged R15)
// ---------------------------------------------------------------------------
__global__ __launch_bounds__(256)
void prep_w(const float* __restrict__ lora_A,   // [64][4096]
            const float* __restrict__ lora_B,   // [4096][64]
            const float* __restrict__ absmax,   // [262144]
            const int*   __restrict__ codes) {  // [4096][4096]
    constexpr int PAD = 132;
    float* sBt = reinterpret_cast<float*>(smem_raw);  // [64][132] B^T
    float* sA  = sBt + 64 * PAD;                      // [64][132] A
    const int b = blockIdx.x, tid = threadIdx.x;
    const int n0 = (b >> 5) * 128, k0 = (b & 31) * 128;

    for (int idx = tid; idx < 128 * 16; idx += 256) {
        int row = idx & 127, rq = idx >> 7;
        float4 v = *reinterpret_cast<const float4*>(&lora_B[(size_t)(n0 + row) * R_DIM + rq * 4]);
        sBt[(rq * 4 + 0) * PAD + row] = v.x;
        sBt[(rq * 4 + 1) * PAD + row] = v.y;
        sBt[(rq * 4 + 2) * PAD + row] = v.z;
        sBt[(rq * 4 + 3) * PAD + row] = v.w;
    }
    for (int idx = tid; idx < 64 * 32; idx += 256) {
        int r = idx >> 5, c4 = idx & 31;
        *reinterpret_cast<float4*>(&sA[r * PAD + c4 * 4]) =
            *reinterpret_cast<const float4*>(&lora_A[(size_t)r * IN_DIM + k0 + c4 * 4]);
    }
    __syncthreads();

    const int ty = tid >> 4, tx = tid & 15;           // 16x16 thread grid
    float acc[8][8];
#pragma unroll
    for (int i = 0; i < 8; i++)
#pragma unroll
        for (int j = 0; j < 8; j++) acc[i][j] = 0.0f;

    for (int r = 0; r < R_DIM; r++) {
        float bv[8], av[8];
        float4 b0 = *reinterpret_cast<const float4*>(&sBt[r * PAD + ty * 8]);
        float4 b1 = *reinterpret_cast<const float4*>(&sBt[r * PAD + ty * 8 + 4]);
        float4 a0 = *reinterpret_cast<const float4*>(&sA[r * PAD + tx * 8]);
        float4 a1 = *reinterpret_cast<const float4*>(&sA[r * PAD + tx * 8 + 4]);
        bv[0] = b0.x; bv[1] = b0.y; bv[2] = b0.z; bv[3] = b0.w;
        bv[4] = b1.x; bv[5] = b1.y; bv[6] = b1.z; bv[7] = b1.w;
        av[0] = a0.x; av[1] = a0.y; av[2] = a0.z; av[3] = a0.w;
        av[4] = a1.x; av[5] = a1.y; av[6] = a1.z; av[7] = a1.w;
#pragma unroll
        for (int i = 0; i < 8; i++)
#pragma unroll
            for (int j = 0; j < 8; j++) acc[i][j] = fmaf(bv[i], av[j], acc[i][j]);
    }

#pragma unroll
    for (int i = 0; i < 8; i++) {
        int n = n0 + ty * 8 + i;
        int k = k0 + tx * 8;
        float am = absmax[n * 64 + (k >> 6)];
        const int4* cp = reinterpret_cast<const int4*>(&codes[(size_t)n * IN_DIM + k]);
        int4 c0 = cp[0], c1 = cp[1];
        float4 o0, o1;
        o0.x = rna_tf32(fmaf(c_nf4[c0.x & 15], am, 2.0f * acc[i][0]));
        o0.y = rna_tf32(fmaf(c_nf4[c0.y & 15], am, 2.0f * acc[i][1]));
        o0.z = rna_tf32(fmaf(c_nf4[c0.z & 15], am, 2.0f * acc[i][2]));
        o0.w = rna_tf32(fmaf(c_nf4[c0.w & 15], am, 2.0f * acc[i][3]));
        o1.x = rna_tf32(fmaf(c_nf4[c1.x & 15], am, 2.0f * acc[i][4]));
        o1.y = rna_tf32(fmaf(c_nf4[c1.y & 15], am, 2.0f * acc[i][5]));
        o1.z = rna_tf32(fmaf(c_nf4[c1.z & 15], am, 2.0f * acc[i][6]));
        o1.w = rna_tf32(fmaf(c_nf4[c1.w & 15], am, 2.0f * acc[i][7]));
        float4* op = reinterpret_cast<float4*>(&g_W[(size_t)n * IN_DIM + k]);
        op[0] = o0;
        op[1] = o1;
    }
}

// ---------------------------------------------------------------------------
// Launch 2: main tf32 GEMM  out = x @ W'^T   (K = 4096)
//   NEW shape: CTA 128x128, 128 thr, 4 warps as 2(m)x2(n) of 64x64.
//   BK=32, 3 stages, 2 CTAs/SM (110 KB smem), GROUP=8 swizzle, SA=36.
//   Halves LDSM read amplification (A x2, B x2) vs the 64x32 shape and
//   doubles per-warp MMA ILP (32 indep MMAs per ks batch).
//   ldmatrix.x4 fragments (conflict-free) + ks double-buffer + kt unroll 3.
//   A reads raw x (HW tf32 truncation in the MMA).
// ---------------------------------------------------------------------------
__global__ __launch_bounds__(128, 2)
void gemm_main(const float* __restrict__ x, float* __restrict__ out) {
    constexpr int BM = 128, BN = 128, SA = 36, STAGES = 3;
    constexpr int MT = 4, NT = 8;                 // warp tile 64x64
    constexpr int GROUP = 8, NBLK = OUT_DIM / BN; // 32
    constexpr int SAB = SA * 4;                   // 144 B row stride
    constexpr int A_STAGE_B = BM * SAB;           // 18432 B
    constexpr int B_STAGE_B = BN * SAB;
    constexpr int NK = IN_DIM / 32;               // 128 kt iterations

    float* smem = reinterpret_cast<float*>(smem_raw);
    float* sA = smem;                             // [3][128*36]
    float* sB = smem + STAGES * BM * SA;          // [3][128*36]

    const int tid = threadIdx.x, lane = tid & 31, wid = tid >> 5;
    const int wm = wid & 1, wn = wid >> 1;        // 2 x 2 warps
    const int lr = lane >> 2, lc = lane & 3;

    const int bid = blockIdx.x;
    const int grp = bid / (GROUP * NBLK);
    const int rem = bid % (GROUP * NBLK);
    const int m0 = (grp * GROUP + rem % GROUP) * BM;
    const int n0 = (rem / GROUP) * BN;

    const float* gA = x + (size_t)m0 * IN_DIM;
    const float* gB = g_W + (size_t)n0 * IN_DIM;

    const uint32_t sA_u = (uint32_t)__cvta_generic_to_shared(sA);
    const uint32_t sB_u = (uint32_t)__cvta_generic_to_shared(sB);
    // A ldmatrix.x4 (per mt): mats (r0-7,c0-3),(r8-15,c0-3),(r0-7,c4-7),(r8-15,c4-7)
    const uint32_t aAddr0 = sA_u + (uint32_t)(((wm * 64 + (lane & 15)) * SA + (lane >> 4) * 4) * 4);
    // B ldmatrix.x4 (per nt-pair p): mats (nt0,c0-3),(nt0,c4-7),(nt1,c0-3),(nt1,c4-7)
    const uint32_t bAddr0 = sB_u + (uint32_t)(((wn * 64 + ((lane >> 4) << 3) + (lane & 7)) * SA
                                               + ((lane >> 3) & 1) * 4) * 4);

    float c[MT][NT][4];
#pragma unroll
    for (int mt = 0; mt < MT; mt++)
#pragma unroll
        for (int nt = 0; nt < NT; nt++)
#pragma unroll
            for (int q = 0; q < 4; q++) c[mt][nt][q] = 0.0f;

    // Per-thread cp.async coordinates (fixed): 128 threads, 8 rows apart
    const int ld_row = tid >> 3, ld_col = (tid & 7) * 4;  // rows 0..15

    auto load_stage = [&](int s, int kt) {
        const int kk = kt * 32;
        float* dA = sA + s * BM * SA;
        float* dB = sB + s * BN * SA;
#pragma unroll
        for (int i = 0; i < 8; i++) {             // A: 1024 chunks / 128 thr
            int row = ld_row + 16 * i;
            cp_async16(dA + row * SA + ld_col, gA + (size_t)row * IN_DIM + kk + ld_col);
        }
#pragma unroll
        for (int i = 0; i < 8; i++) {             // B: 1024 chunks
            int row = ld_row + 16 * i;
            cp_async16(dB + row * SA + ld_col, gB + (size_t)row * IN_DIM + kk + ld_col);
        }
    };

    uint32_t af[2][MT][4], bf[2][NT][2];

    auto load_frags = [&](int s, int ks, int buf) {
        uint32_t aS = aAddr0 + s * A_STAGE_B + ks * 32;
        uint32_t bS = bAddr0 + s * B_STAGE_B + ks * 32;
#pragma unroll
        for (int mt = 0; mt < MT; mt++)
            LDSM_X4(af[buf][mt][0], af[buf][mt][1], af[buf][mt][2], af[buf][mt][3],
                    aS + mt * 16 * SAB);
#pragma unroll
        for (int p = 0; p < 4; p++)
            LDSM_X4(bf[buf][2 * p][0], bf[buf][2 * p][1],
                    bf[buf][2 * p + 1][0], bf[buf][2 * p + 1][1],
                    bS + p * 16 * SAB);
    };

    // One kt iteration with compile-time stage indices.
    auto kt_iter = [&](int kt, int s, int ls_stage, bool do_load) {
        load_frags(s, 0, 0);                      // ks0 LDSM first (overlaps cp.async)
        if (do_load) load_stage(ls_stage, kt + 2);
        cp_commit();
#pragma unroll
        for (int ks = 0; ks < 4; ks++) {
            int cur = ks & 1;
            if (ks < 3) load_frags(s, ks + 1, cur ^ 1);
#pragma unroll
            for (int mt = 0; mt < MT; mt++)
#pragma unroll
                for (int nt = 0; nt < NT; nt++)
                    mma_tf32(c[mt][nt], af[cur][mt], bf[cur][nt]);
        }
        cp_wait<1>();
        __syncthreads();
    };

    load_stage(0, 0); cp_commit();
    load_stage(1, 1); cp_commit();
    cp_wait<1>();
    __syncthreads();

    // Steady state: kt in [0,126), unrolled by 3 with constant stage indices
    for (int kt = 0; kt < NK - 2; kt += 3) {
        kt_iter(kt,     0, 2, true);
        kt_iter(kt + 1, 1, 0, true);
        kt_iter(kt + 2, 2, 1, true);
    }
    // Tail: kt = 126 (s=0), kt = 127 (s=1); no further loads
    kt_iter(NK - 2, 0, 2, false);
    kt_iter(NK - 1, 1, 0, false);

    // Epilogue
#pragma unroll
    for (int mt = 0; mt < MT; mt++) {
        int r0 = m0 + wm * 64 + mt * 16 + lr;
#pragma unroll
        for (int nt = 0; nt < NT; nt++) {
            int cc = n0 + wn * 64 + nt * 8 + 2 * lc;
            *reinterpret_cast<float2*>(&out[(size_t)r0 * OUT_DIM + cc]) =
                make_float2(c[mt][nt][0], c[mt][nt][1]);
            *reinterpret_cast<float2*>(&out[(size_t)(r0 + 8) * OUT_DIM + cc]) =
                make_float2(c[mt][nt][2], c[mt][nt][3]);
        }
    }
}

// ---------------------------------------------------------------------------
// Host
// ---------------------------------------------------------------------------
extern "C" void kernel_launch(void* const* d_in, const int* in_sizes, int n_in,
                              void* d_out, int out_size) {
    const float* x      = (const float*)d_in[0];
    const float* lora_A = (const float*)d_in[1];
    const float* lora_B = (const float*)d_in[2];
    const float* absmax = (const float*)d_in[3];
    const int*   codes  = (const int*)d_in[4];
    float* out = (float*)d_out;

    constexpr int SMEM_PREP = 2 * 64 * 132 * 4;          //  67584
    constexpr int SMEM_MAIN = 3 * (128 + 128) * 36 * 4;  // 110592 -> 2 CTA/SM
    static bool attr_done = false;
    if (!attr_done) {
        cudaFuncSetAttribute((const void*)prep_w,
                             cudaFuncAttributeMaxDynamicSharedMemorySize, SMEM_PREP);
        cudaFuncSetAttribute((const void*)gemm_main,
                             cudaFuncAttributeMaxDynamicSharedMemorySize, SMEM_MAIN);
        attr_done = true;
    }

    // 1) W' = rna(deq + 2 B@A)
    prep_w<<<1024, 256, SMEM_PREP>>>(lora_A, lora_B, absmax, codes);

    // 2) out = x @ W'^T  (x fed raw; tf32 truncation happens in the MMA)
    gemm_main<<<(M_TOTAL / 128) * (OUT_DIM / 128), 128, SMEM_MAIN>>>(x, out);
}

// round 17
// speedup vs baseline: 1.1243x; 1.0001x over previous
#include <cuda_runtime.h>
#include <cstdint>

// ---------------------------------------------------------------------------
// Problem constants
// ---------------------------------------------------------------------------
#define OUT_DIM 4096
#define IN_DIM  4096
#define M_TOTAL 8192                 // 4 * 2048
#define R_DIM   64

// Scratch (allocation-free rule), plain row-major layout.
// W' = rna_tf32( dequant_nf4(W) + 2 * lora_B @ lora_A )
__device__ float g_W[(size_t)OUT_DIM * IN_DIM];

__constant__ float c_nf4[16] = {
    -1.0f, -0.6961928009986877f, -0.5250730514526367f, -0.39491748809814453f,
    -0.28444138169288635f, -0.18477343022823334f, -0.09105003625154495f, 0.0f,
    0.07958029955625534f, 0.16093020141124725f, 0.24611230194568634f, 0.33791524171829224f,
    0.44070982933044434f, 0.5626170039176941f, 0.7229568362236023f, 1.0f};

// ---------------------------------------------------------------------------
// Helpers
// ---------------------------------------------------------------------------
__device__ __forceinline__ float rna_tf32(float v) {
    uint32_t r;
    asm("cvt.rna.tf32.f32 %0, %1;" : "=r"(r) : "f"(v));
    return __uint_as_float(r);
}

__device__ __forceinline__ void cp_async16(void* smem_dst, const void* gptr) {
    uint32_t s = (uint32_t)__cvta_generic_to_shared(smem_dst);
    asm volatile("cp.async.cg.shared.global [%0], [%1], 16;" :: "r"(s), "l"(gptr));
}
__device__ __forceinline__ void cp_commit() {
    asm volatile("cp.async.commit_group;" ::: "memory");
}
template <int N>
__device__ __forceinline__ void cp_wait() {
    asm volatile("cp.async.wait_group %0;" :: "n"(N) : "memory");
}

// tf32: D += A(16x8) * B(8x8)
// NOTE: raw fp32 bits in operands are consumed as tf32 via HW truncation.
__device__ __forceinline__ void mma_tf32(float* c, const uint32_t* a, const uint32_t* b) {
    asm volatile(
        "mma.sync.aligned.m16n8k8.row.col.f32.tf32.tf32.f32 "
        "{%0,%1,%2,%3}, {%4,%5,%6,%7}, {%8,%9}, {%0,%1,%2,%3};"
        : "+f"(c[0]), "+f"(c[1]), "+f"(c[2]), "+f"(c[3])
        : "r"(a[0]), "r"(a[1]), "r"(a[2]), "r"(a[3]), "r"(b[0]), "r"(b[1]));
}

// ldmatrix x4: four 8x8xb16 tiles (== 8x4xb32), lane l gets b32 (row l/4, col l%4)
#define LDSM_X4(r0, r1, r2, r3, addr) \
    asm volatile("ldmatrix.sync.aligned.m8n8.x4.shared.b16 {%0,%1,%2,%3}, [%4];" \
                 : "=r"(r0), "=r"(r1), "=r"(r2), "=r"(r3) : "r"(addr))

extern __shared__ char smem_raw[];

// ---------------------------------------------------------------------------
// Launch 1: prep_w — W' 128x128 tiles = rna(deq_nf4 + 2*B@A)  (unchanged)
// ---------------------------------------------------------------------------
__global__ __launch_bounds__(256)
void prep_w(const float* __restrict__ lora_A,   // [64][4096]
            const float* __restrict__ lora_B,   // [4096][64]
            const float* __restrict__ absmax,   // [262144]
            const int*   __restrict__ codes) {  // [4096][4096]
    constexpr int PAD = 132;
    float* sBt = reinterpret_cast<float*>(smem_raw);  // [64][132] B^T
    float* sA  = sBt + 64 * PAD;                      // [64][132] A
    const int b = blockIdx.x, tid = threadIdx.x;
    const int n0 = (b >> 5) * 128, k0 = (b & 31) * 128;

    for (int idx = tid; idx < 128 * 16; idx += 256) {
        int row = idx & 127, rq = idx >> 7;
        float4 v = *reinterpret_cast<const float4*>(&lora_B[(size_t)(n0 + row) * R_DIM + rq * 4]);
        sBt[(rq * 4 + 0) * PAD + row] = v.x;
        sBt[(rq * 4 + 1) * PAD + row] = v.y;
        sBt[(rq * 4 + 2) * PAD + row] = v.z;
        sBt[(rq * 4 + 3) * PAD + row] = v.w;
    }
    for (int idx = tid; idx < 64 * 32; idx += 256) {
        int r = idx >> 5, c4 = idx & 31;
        *reinterpret_cast<float4*>(&sA[r * PAD + c4 * 4]) =
            *reinterpret_cast<const float4*>(&lora_A[(size_t)r * IN_DIM + k0 + c4 * 4]);
    }
    __syncthreads();

    const int ty = tid >> 4, tx = tid & 15;           // 16x16 thread grid
    float acc[8][8];
#pragma unroll
    for (int i = 0; i < 8; i++)
#pragma unroll
        for (int j = 0; j < 8; j++) acc[i][j] = 0.0f;

    for (int r = 0; r < R_DIM; r++) {
        float bv[8], av[8];
        float4 b0 = *reinterpret_cast<const float4*>(&sBt[r * PAD + ty * 8]);
        float4 b1 = *reinterpret_cast<const float4*>(&sBt[r * PAD + ty * 8 + 4]);
        float4 a0 = *reinterpret_cast<const float4*>(&sA[r * PAD + tx * 8]);
        float4 a1 = *reinterpret_cast<const float4*>(&sA[r * PAD + tx * 8 + 4]);
        bv[0] = b0.x; bv[1] = b0.y; bv[2] = b0.z; bv[3] = b0.w;
        bv[4] = b1.x; bv[5] = b1.y; bv[6] = b1.z; bv[7] = b1.w;
        av[0] = a0.x; av[1] = a0.y; av[2] = a0.z; av[3] = a0.w;
        av[4] = a1.x; av[5] = a1.y; av[6] = a1.z; av[7] = a1.w;
#pragma unroll
        for (int i = 0; i < 8; i++)
#pragma unroll
            for (int j = 0; j < 8; j++) acc[i][j] = fmaf(bv[i], av[j], acc[i][j]);
    }

#pragma unroll
    for (int i = 0; i < 8; i++) {
        int n = n0 + ty * 8 + i;
        int k = k0 + tx * 8;
        float am = absmax[n * 64 + (k >> 6)];
        const int4* cp = reinterpret_cast<const int4*>(&codes[(size_t)n * IN_DIM + k]);
        int4 c0 = cp[0], c1 = cp[1];
        float4 o0, o1;
        o0.x = rna_tf32(fmaf(c_nf4[c0.x & 15], am, 2.0f * acc[i][0]));
        o0.y = rna_tf32(fmaf(c_nf4[c0.y & 15], am, 2.0f * acc[i][1]));
        o0.z = rna_tf32(fmaf(c_nf4[c0.z & 15], am, 2.0f * acc[i][2]));
        o0.w = rna_tf32(fmaf(c_nf4[c0.w & 15], am, 2.0f * acc[i][3]));
        o1.x = rna_tf32(fmaf(c_nf4[c1.x & 15], am, 2.0f * acc[i][4]));
        o1.y = rna_tf32(fmaf(c_nf4[c1.y & 15], am, 2.0f * acc[i][5]));
        o1.z = rna_tf32(fmaf(c_nf4[c1.z & 15], am, 2.0f * acc[i][6]));
        o1.w = rna_tf32(fmaf(c_nf4[c1.w & 15], am, 2.0f * acc[i][7]));
        float4* op = reinterpret_cast<float4*>(&g_W[(size_t)n * IN_DIM + k]);
        op[0] = o0;
        op[1] = o1;
    }
}

// ---------------------------------------------------------------------------
// Launch 2: main tf32 GEMM  out = x @ W'^T   (K = 4096)
//   R16 shape: CTA 128x128, 128 thr, 4 warps as 2(m)x2(n) of 64x64,
//   BK=32, 3 stages, 2 CTAs/SM, GROUP=8 swizzle, SA=36 pad,
//   ldmatrix.x4 + ks double-buffer + kt unroll by 3.
//   NEW: cp_wait + __syncthreads moved BEFORE the final (ks=3) MMA batch —
//   ks3 operands are already in registers, and the next stage written after
//   the barrier is (s+2)%3 != registers, so the reorder is hazard-free.
//   The 32-MMA ks3 batch now hides the barrier convoy + next-kt LDSM ramp.
// ---------------------------------------------------------------------------
__global__ __launch_bounds__(128, 2)
void gemm_main(const float* __restrict__ x, float* __restrict__ out) {
    constexpr int BM = 128, BN = 128, SA = 36, STAGES = 3;
    constexpr int MT = 4, NT = 8;                 // warp tile 64x64
    constexpr int GROUP = 8, NBLK = OUT_DIM / BN; // 32
    constexpr int SAB = SA * 4;                   // 144 B row stride
    constexpr int A_STAGE_B = BM * SAB;           // 18432 B
    constexpr int B_STAGE_B = BN * SAB;
    constexpr int NK = IN_DIM / 32;               // 128 kt iterations

    float* smem = reinterpret_cast<float*>(smem_raw);
    float* sA = smem;                             // [3][128*36]
    float* sB = smem + STAGES * BM * SA;          // [3][128*36]

    const int tid = threadIdx.x, lane = tid & 31, wid = tid >> 5;
    const int wm = wid & 1, wn = wid >> 1;        // 2 x 2 warps
    const int lr = lane >> 2, lc = lane & 3;

    const int bid = blockIdx.x;
    const int grp = bid / (GROUP * NBLK);
    const int rem = bid % (GROUP * NBLK);
    const int m0 = (grp * GROUP + rem % GROUP) * BM;
    const int n0 = (rem / GROUP) * BN;

    const float* gA = x + (size_t)m0 * IN_DIM;
    const float* gB = g_W + (size_t)n0 * IN_DIM;

    const uint32_t sA_u = (uint32_t)__cvta_generic_to_shared(sA);
    const uint32_t sB_u = (uint32_t)__cvta_generic_to_shared(sB);
    const uint32_t aAddr0 = sA_u + (uint32_t)(((wm * 64 + (lane & 15)) * SA + (lane >> 4) * 4) * 4);
    const uint32_t bAddr0 = sB_u + (uint32_t)(((wn * 64 + ((lane >> 4) << 3) + (lane & 7)) * SA
                                               + ((lane >> 3) & 1) * 4) * 4);

    float c[MT][NT][4];
#pragma unroll
    for (int mt = 0; mt < MT; mt++)
#pragma unroll
        for (int nt = 0; nt < NT; nt++)
#pragma unroll
            for (int q = 0; q < 4; q++) c[mt][nt][q] = 0.0f;

    // Per-thread cp.async coordinates (fixed): 128 threads, 16 rows/pass
    const int ld_row = tid >> 3, ld_col = (tid & 7) * 4;

    auto load_stage = [&](int s, int kt) {
        const int kk = kt * 32;
        float* dA = sA + s * BM * SA;
        float* dB = sB + s * BN * SA;
#pragma unroll
        for (int i = 0; i < 8; i++) {             // A: 1024 chunks / 128 thr
            int row = ld_row + 16 * i;
            cp_async16(dA + row * SA + ld_col, gA + (size_t)row * IN_DIM + kk + ld_col);
        }
#pragma unroll
        for (int i = 0; i < 8; i++) {             // B: 1024 chunks
            int row = ld_row + 16 * i;
            cp_async16(dB + row * SA + ld_col, gB + (size_t)row * IN_DIM + kk + ld_col);
        }
    };

    uint32_t af[2][MT][4], bf[2][NT][2];

    auto load_frags = [&](int s, int ks, int buf) {
        uint32_t aS = aAddr0 + s * A_STAGE_B + ks * 32;
        uint32_t bS = bAddr0 + s * B_STAGE_B + ks * 32;
#pragma unroll
        for (int mt = 0; mt < MT; mt++)
            LDSM_X4(af[buf][mt][0], af[buf][mt][1], af[buf][mt][2], af[buf][mt][3],
                    aS + mt * 16 * SAB);
#pragma unroll
        for (int p = 0; p < 4; p++)
            LDSM_X4(bf[buf][2 * p][0], bf[buf][2 * p][1],
                    bf[buf][2 * p + 1][0], bf[buf][2 * p + 1][1],
                    bS + p * 16 * SAB);
    };

    // One kt iteration with compile-time stage indices.
    // Barrier is hoisted BEFORE the ks=3 MMA batch (operands already in regs).
    auto kt_iter = [&](int kt, int s, int ls_stage, bool do_load) {
        load_frags(s, 0, 0);                      // ks0 LDSM first (overlaps cp.async)
        if (do_load) load_stage(ls_stage, kt + 2);
        cp_commit();
#pragma unroll
        for (int ks = 0; ks < 4; ks++) {
            int cur = ks & 1;
            if (ks < 3) load_frags(s, ks + 1, cur ^ 1);
            if (ks == 3) {                        // hide barrier behind last batch
                cp_wait<1>();
                __syncthreads();
            }
#pragma unroll
            for (int mt = 0; mt < MT; mt++)
#pragma unroll
                for (int nt = 0; nt < NT; nt++)
                    mma_tf32(c[mt][nt], af[cur][mt], bf[cur][nt]);
        }
    };

    load_stage(0, 0); cp_commit();
    load_stage(1, 1); cp_commit();
    cp_wait<1>();
    __syncthreads();

    // Steady state: kt in [0,126), unrolled by 3 with constant stage indices
    for (int kt = 0; kt < NK - 2; kt += 3) {
        kt_iter(kt,     0, 2, true);
        kt_iter(kt + 1, 1, 0, true);
        kt_iter(kt + 2, 2, 1, true);
    }
    // Tail: kt = 126 (s=0), kt = 127 (s=1); no further loads
    kt_iter(NK - 2, 0, 2, false);
    kt_iter(NK - 1, 1, 0, false);

    // Epilogue
#pragma unroll
    for (int mt = 0; mt < MT; mt++) {
        int r0 = m0 + wm * 64 + mt * 16 + lr;
#pragma unroll
        for (int nt = 0; nt < NT; nt++) {
            int cc = n0 + wn * 64 + nt * 8 + 2 * lc;
            *reinterpret_cast<float2*>(&out[(size_t)r0 * OUT_DIM + cc]) =
                make_float2(c[mt][nt][0], c[mt][nt][1]);
            *reinterpret_cast<float2*>(&out[(size_t)(r0 + 8) * OUT_DIM + cc]) =
                make_float2(c[mt][nt][2], c[mt][nt][3]);
        }
    }
}

// ---------------------------------------------------------------------------
// Host
// ---------------------------------------------------------------------------
extern "C" void kernel_launch(void* const* d_in, const int* in_sizes, int n_in,
                              void* d_out, int out_size) {
    const float* x      = (const float*)d_in[0];
    const float* lora_A = (const float*)d_in[1];
    const float* lora_B = (const float*)d_in[2];
    const float* absmax = (const float*)d_in[3];
    const int*   codes  = (const int*)d_in[4];
    float* out = (float*)d_out;

    constexpr int SMEM_PREP = 2 * 64 * 132 * 4;          //  67584
    constexpr int SMEM_MAIN = 3 * (128 + 128) * 36 * 4;  // 110592 -> 2 CTA/SM
    static bool attr_done = false;
    if (!attr_done) {
        cudaFuncSetAttribute((const void*)prep_w,
                             cudaFuncAttributeMaxDynamicSharedMemorySize, SMEM_PREP);
        cudaFuncSetAttribute((const void*)gemm_main,
                             cudaFuncAttributeMaxDynamicSharedMemorySize, SMEM_MAIN);
        attr_done = true;
    }

    // 1) W' = rna(deq + 2 B@A)
    prep_w<<<1024, 256, SMEM_PREP>>>(lora_A, lora_B, absmax, codes);

    // 2) out = x @ W'^T  (x fed raw; tf32 truncation happens in the MMA)
    gemm_main<<<(M_TOTAL / 128) * (OUT_DIM / 128), 128, SMEM_MAIN>>>(x, out);
}